// round 2
// baseline (speedup 1.0000x reference)
#include <cuda_runtime.h>

#define D      64
#define NSEG   8192
#define SEGS   16   // segments per block in kernel 2

// Scratch: per-segment maxes for both types. 2*8192*64*4 = 4 MB.
__device__ float g_segmax[2 * NSEG * D];

// ---------------------------------------------------------------------------
// Kernel 1: per-segment max over contiguous row ranges (CSR), fully coalesced.
// One block (256 threads) per segment. Thread layout: 16 float4-columns x
// 16 row-groups; each outer iteration streams 32 rows (8 KB) per block
// (2 independent loads in flight per thread before the fmax chain).
// NOTE: ptr arrays are int32 (JAX x64 disabled downcasts the int64 ptr).
// ---------------------------------------------------------------------------
__global__ void __launch_bounds__(256, 8)
seg_max_kernel(const float* __restrict__ x_a,
               const float* __restrict__ x_b,
               const int* __restrict__ ptr_a,
               const int* __restrict__ ptr_b,
               float* __restrict__ out)
{
    const int bid  = blockIdx.x;               // [0, 2*NSEG)
    const int type = (bid >= NSEG) ? 1 : 0;
    const int g    = type ? (bid - NSEG) : bid;

    const float*   x   = type ? x_b   : x_a;
    const int*     ptr = type ? ptr_b : ptr_a;

    const int s = ptr[g];
    const int e = ptr[g + 1];

    const int tid = threadIdx.x;               // 256
    const int c4  = tid & 15;                  // float4 column 0..15
    const int rg  = tid >> 4;                  // row group 0..15

    const float NEG = -3.402823466e38f;
    float4 m0 = make_float4(NEG, NEG, NEG, NEG);
    float4 m1 = make_float4(NEG, NEG, NEG, NEG);

    const float4* __restrict__ xv = reinterpret_cast<const float4*>(x);

    long long row = (long long)s + rg;
    // main loop: 2 rows per thread per iteration (rows row and row+16)
    for (; row + 16 < e; row += 32) {
        float4 v0 = xv[row * (D / 4) + c4];
        float4 v1 = xv[(row + 16) * (D / 4) + c4];
        m0.x = fmaxf(m0.x, v0.x); m0.y = fmaxf(m0.y, v0.y);
        m0.z = fmaxf(m0.z, v0.z); m0.w = fmaxf(m0.w, v0.w);
        m1.x = fmaxf(m1.x, v1.x); m1.y = fmaxf(m1.y, v1.y);
        m1.z = fmaxf(m1.z, v1.z); m1.w = fmaxf(m1.w, v1.w);
    }
    if (row < e) {
        float4 v0 = xv[row * (D / 4) + c4];
        m0.x = fmaxf(m0.x, v0.x); m0.y = fmaxf(m0.y, v0.y);
        m0.z = fmaxf(m0.z, v0.z); m0.w = fmaxf(m0.w, v0.w);
    }
    m0.x = fmaxf(m0.x, m1.x); m0.y = fmaxf(m0.y, m1.y);
    m0.z = fmaxf(m0.z, m1.z); m0.w = fmaxf(m0.w, m1.w);

    __shared__ float4 sm[16][16];
    sm[rg][c4] = m0;
    __syncthreads();

    if (tid < 16) {
        float4 m = sm[0][tid];
        #pragma unroll
        for (int j = 1; j < 16; j++) {
            float4 v = sm[j][tid];
            m.x = fmaxf(m.x, v.x);
            m.y = fmaxf(m.y, v.y);
            m.z = fmaxf(m.z, v.z);
            m.w = fmaxf(m.w, v.w);
        }
        float4* dst = reinterpret_cast<float4*>(
            &g_segmax[(size_t)(type * NSEG + g) * D]);
        dst[tid] = m;
    }

    // Initialize output to 0 (== relu floor). Kernel 2 runs after this kernel
    // completes (stream order), so this is safely ordered before its atomics.
    if (bid == 0 && tid < 128) out[tid] = 0.0f;
}

// ---------------------------------------------------------------------------
// Kernel 2: per-segment 64->128 linear + relu + global max.
// One block (128 threads) handles SEGS segments of one type. Thread o keeps
// W row o in registers; segment maxes staged in shared (broadcast LDS).
// relu(max_g h) == max_g max(0, h), and int-bit atomicMax is exact ordering
// for non-negative IEEE floats.
// ---------------------------------------------------------------------------
__global__ void __launch_bounds__(128)
gemm_max_kernel(const float* __restrict__ W_a,
                const float* __restrict__ W_b,
                const float* __restrict__ b_a,
                const float* __restrict__ b_b,
                float* __restrict__ out)
{
    const int blocks_per_type = NSEG / SEGS;          // 512
    const int bid   = blockIdx.x;                     // [0, 1024)
    const int type  = (bid >= blocks_per_type) ? 1 : 0;
    const int gbase = (type ? (bid - blocks_per_type) : bid) * SEGS;

    const float* __restrict__ W    = type ? W_b : W_a;
    const float* __restrict__ bias = type ? b_b : b_a;

    const int o = threadIdx.x;                        // output channel 0..127

    float w[D];
    #pragma unroll
    for (int k = 0; k < D; k++) w[k] = W[o * D + k];
    const float bo = bias[o];

    __shared__ float sm[SEGS][D];
    {
        const float* src = &g_segmax[(size_t)(type * NSEG + gbase) * D];
        for (int i = threadIdx.x; i < SEGS * D; i += blockDim.x)
            sm[i / D][i % D] = src[i];
    }
    __syncthreads();

    float lmax = 0.0f;  // relu floor
    #pragma unroll
    for (int s = 0; s < SEGS; s++) {
        float acc = bo;
        #pragma unroll
        for (int k = 0; k < D; k++)
            acc = fmaf(w[k], sm[s][k], acc);
        lmax = fmaxf(lmax, acc);
    }

    atomicMax(reinterpret_cast<int*>(out) + o, __float_as_int(lmax));
}

// ---------------------------------------------------------------------------
extern "C" void kernel_launch(void* const* d_in, const int* in_sizes, int n_in,
                              void* d_out, int out_size)
{
    const float* x_a   = (const float*)d_in[0];
    const float* x_b   = (const float*)d_in[1];
    const float* W_a   = (const float*)d_in[2];
    const float* W_b   = (const float*)d_in[3];
    const float* b_a   = (const float*)d_in[4];
    const float* b_b   = (const float*)d_in[5];
    const int*   ptr_a = (const int*)d_in[6];
    const int*   ptr_b = (const int*)d_in[7];
    float* out = (float*)d_out;

    seg_max_kernel<<<2 * NSEG, 256>>>(x_a, x_b, ptr_a, ptr_b, out);
    gemm_max_kernel<<<2 * (NSEG / SEGS), 128>>>(W_a, W_b, b_a, b_b, out);
}

// round 3
// speedup vs baseline: 1.1832x; 1.1832x over previous
#include <cuda_runtime.h>

#define D      64
#define NSEG   8192
#define SEGS   16   // segments per block in kernel 2

// Scratch: per-segment maxes for both types. 2*8192*64*4 = 4 MB.
__device__ float g_segmax[2 * NSEG * D];

__device__ __forceinline__ void fmax4(float4& a, const float4 b) {
    a.x = fmaxf(a.x, b.x); a.y = fmaxf(a.y, b.y);
    a.z = fmaxf(a.z, b.z); a.w = fmaxf(a.w, b.w);
}

// ---------------------------------------------------------------------------
// Kernel 1: per-segment max over contiguous row ranges (CSR), fully coalesced.
// One block (256 threads) per segment. Thread layout: 16 float4-columns x
// 16 row-groups. Main loop keeps 4 independent row loads (rows +0,+16,+32,+48)
// in flight per thread (MLP=4) with __ldcs (streaming, one-pass data).
// ptr arrays are int32 (JAX x64 disabled downcasts the int64 ptr).
// ---------------------------------------------------------------------------
__global__ void __launch_bounds__(256)
seg_max_kernel(const float* __restrict__ x_a,
               const float* __restrict__ x_b,
               const int* __restrict__ ptr_a,
               const int* __restrict__ ptr_b,
               float* __restrict__ out)
{
    const int bid  = blockIdx.x;               // [0, 2*NSEG)
    const int type = (bid >= NSEG) ? 1 : 0;
    const int g    = type ? (bid - NSEG) : bid;

    const float* x   = type ? x_b   : x_a;
    const int*   ptr = type ? ptr_b : ptr_a;

    const int s = ptr[g];
    const int e = ptr[g + 1];

    const int tid = threadIdx.x;               // 256
    const int c4  = tid & 15;                  // float4 column 0..15
    const int rg  = tid >> 4;                  // row group 0..15

    const float NEG = -3.402823466e38f;
    float4 m0 = make_float4(NEG, NEG, NEG, NEG);
    float4 m1 = m0, m2 = m0, m3 = m0;

    const float4* __restrict__ xv = reinterpret_cast<const float4*>(x);

    long long row = (long long)s + rg;
    // main loop: 4 rows per thread per iteration (rows +0, +16, +32, +48)
    for (; row + 48 < e; row += 64) {
        const float4* p = xv + row * (D / 4) + c4;
        float4 v0 = __ldcs(p);
        float4 v1 = __ldcs(p + 16 * (D / 4));
        float4 v2 = __ldcs(p + 32 * (D / 4));
        float4 v3 = __ldcs(p + 48 * (D / 4));
        fmax4(m0, v0); fmax4(m1, v1); fmax4(m2, v2); fmax4(m3, v3);
    }
    // tail: one 16-row step at a time
    for (; row < e; row += 16) {
        float4 v0 = __ldcs(xv + row * (D / 4) + c4);
        fmax4(m0, v0);
    }
    fmax4(m0, m1); fmax4(m2, m3); fmax4(m0, m2);

    __shared__ float4 sm[16][16];
    sm[rg][c4] = m0;
    __syncthreads();

    if (tid < 16) {
        float4 m = sm[0][tid];
        #pragma unroll
        for (int j = 1; j < 16; j++)
            fmax4(m, sm[j][tid]);
        float4* dst = reinterpret_cast<float4*>(
            &g_segmax[(size_t)(type * NSEG + g) * D]);
        dst[tid] = m;
    }

    // Initialize output to 0 (== relu floor). Kernel 2 runs after this kernel
    // completes (stream order), so this is safely ordered before its atomics.
    if (bid == 0 && tid < 128) out[tid] = 0.0f;
}

// ---------------------------------------------------------------------------
// Kernel 2: per-segment 64->128 linear + relu + global max.
// One block (128 threads) handles SEGS segments of one type. Thread o keeps
// W row o in registers; segment maxes staged in shared as float4 (broadcast
// LDS128, 4 FMA per LDS). Two segments processed concurrently with 4 partial
// accumulators each -> 8 independent FMA chains (breaks the lat-4 dep chain).
// relu(max_g h) == max_g max(0, h); int-bit atomicMax is exact ordering for
// non-negative IEEE floats.
// ---------------------------------------------------------------------------
__global__ void __launch_bounds__(128)
gemm_max_kernel(const float* __restrict__ W_a,
                const float* __restrict__ W_b,
                const float* __restrict__ b_a,
                const float* __restrict__ b_b,
                float* __restrict__ out)
{
    const int blocks_per_type = NSEG / SEGS;          // 512
    const int bid   = blockIdx.x;                     // [0, 1024)
    const int type  = (bid >= blocks_per_type) ? 1 : 0;
    const int gbase = (type ? (bid - blocks_per_type) : bid) * SEGS;

    const float* __restrict__ W    = type ? W_b : W_a;
    const float* __restrict__ bias = type ? b_b : b_a;

    const int o = threadIdx.x;                        // output channel 0..127

    // W row o in registers (as float4 for vector FMA feed)
    float4 w[D / 4];
    {
        const float4* W4 = reinterpret_cast<const float4*>(W + o * D);
        #pragma unroll
        for (int k = 0; k < D / 4; k++) w[k] = W4[k];
    }
    const float bo = bias[o];

    __shared__ float4 sm[SEGS][D / 4];
    {
        const float4* src = reinterpret_cast<const float4*>(
            &g_segmax[(size_t)(type * NSEG + gbase) * D]);
        for (int i = threadIdx.x; i < SEGS * (D / 4); i += blockDim.x)
            sm[i / (D / 4)][i % (D / 4)] = src[i];
    }
    __syncthreads();

    float lmax = 0.0f;  // relu floor
    #pragma unroll
    for (int s = 0; s < SEGS; s += 2) {
        float a0 = 0.f, a1 = 0.f, a2 = 0.f, a3 = 0.f;   // seg s partials
        float c0 = 0.f, c1 = 0.f, c2 = 0.f, c3 = 0.f;   // seg s+1 partials
        #pragma unroll
        for (int k = 0; k < D / 4; k++) {
            float4 u = sm[s][k];
            float4 v = sm[s + 1][k];
            float4 ww = w[k];
            a0 = fmaf(ww.x, u.x, a0);
            a1 = fmaf(ww.y, u.y, a1);
            a2 = fmaf(ww.z, u.z, a2);
            a3 = fmaf(ww.w, u.w, a3);
            c0 = fmaf(ww.x, v.x, c0);
            c1 = fmaf(ww.y, v.y, c1);
            c2 = fmaf(ww.z, v.z, c2);
            c3 = fmaf(ww.w, v.w, c3);
        }
        float hs = bo + ((a0 + a1) + (a2 + a3));
        float ht = bo + ((c0 + c1) + (c2 + c3));
        lmax = fmaxf(lmax, fmaxf(hs, ht));
    }

    atomicMax(reinterpret_cast<int*>(out) + o, __float_as_int(lmax));
}

// ---------------------------------------------------------------------------
extern "C" void kernel_launch(void* const* d_in, const int* in_sizes, int n_in,
                              void* d_out, int out_size)
{
    const float* x_a   = (const float*)d_in[0];
    const float* x_b   = (const float*)d_in[1];
    const float* W_a   = (const float*)d_in[2];
    const float* W_b   = (const float*)d_in[3];
    const float* b_a   = (const float*)d_in[4];
    const float* b_b   = (const float*)d_in[5];
    const int*   ptr_a = (const int*)d_in[6];
    const int*   ptr_b = (const int*)d_in[7];
    float* out = (float*)d_out;

    seg_max_kernel<<<2 * NSEG, 256>>>(x_a, x_b, ptr_a, ptr_b, out);
    gemm_max_kernel<<<2 * (NSEG / SEGS), 128>>>(W_a, W_b, b_a, b_b, out);
}